// round 2
// baseline (speedup 1.0000x reference)
#include <cuda_runtime.h>

// ---------------- static device scratch (no allocations allowed) -------------
#define MAXN 50176
#define MAXE 800256

__device__ __align__(16) float    g_xh[(size_t)MAXN * 64];     // x @ W^T        [N,64]
__device__ __align__(16) float    g_asrc[MAXN * 4];            // att_src . xh   [N,4]
__device__ __align__(16) float    g_adst[MAXN * 4];            // att_dst . xh   [N,4]
__device__ __align__(16) float    g_cnt[MAXN];                 // in-degree      [N]
__device__ __align__(16) float    g_aes[MAXN * 4];             // segsum a_edge  [N,4]
__device__ __align__(16) unsigned g_amax[MAXN * 4];            // encoded segmax [N,4]
__device__ __align__(16) float    g_denom[MAXN * 4];           // softmax denom  [N,4]
__device__ __align__(16) float    g_l[((size_t)MAXE + MAXN) * 4]; // logits->exp [E+N,4]
__device__ __align__(16) float    g_v[64 * 4];                 // folded W_edge/att_edge

// monotonic float<->uint encoding for atomicMax-based segment max
__device__ __forceinline__ unsigned enc_f(float f) {
    unsigned b = __float_as_uint(f);
    return (b & 0x80000000u) ? ~b : (b | 0x80000000u);
}
__device__ __forceinline__ float dec_f(unsigned u) {
    return __uint_as_float((u & 0x80000000u) ? (u & 0x7fffffffu) : ~u);
}
__device__ __forceinline__ float lrelu(float f) { return f > 0.f ? f : 0.2f * f; }

// ---------------- K0: zero scratch + output ---------------------------------
__global__ void k_zero(float* __restrict__ out, int N) {
    int t = blockIdx.x * blockDim.x + threadIdx.x;
    if (t < N * 64) out[t] = 0.f;
    if (t < N)      g_cnt[t] = 0.f;
    if (t < N * 4) { g_aes[t] = 0.f; g_denom[t] = 0.f; g_amax[t] = 0u; }
}

// ---------------- Kv: fold W_edge with att_edge: v[d][h] --------------------
__global__ void k_vedge(const float* __restrict__ We, const float* __restrict__ att_edge) {
    int t = threadIdx.x;           // exactly 256 = 64 d * 4 h
    int d = t >> 2, h = t & 3;
    float s = 0.f;
#pragma unroll
    for (int c = 0; c < 16; c++)
        s += We[(h * 16 + c) * 64 + d] * att_edge[h * 16 + c];
    g_v[d * 4 + h] = s;
}

// ---------------- K1: xh = x @ W^T  (shared-tiled) ---------------------------
__global__ void k_xh(const float* __restrict__ x, const float* __restrict__ W, int N) {
    __shared__ float sW[64][132];   // padded: conflict-free LDS.128
    __shared__ float sX[16][132];
    int tid = threadIdx.x;          // 256
    for (int i = tid; i < 64 * 32; i += 256) {
        int r = i >> 5, c4 = i & 31;
        float4 w = ((const float4*)W)[r * 32 + c4];
        *(float4*)&sW[r][c4 * 4] = w;
    }
    int ch = tid & 63, g = tid >> 6;
    int tiles = (N + 15) >> 4;
    for (int tile = blockIdx.x; tile < tiles; tile += gridDim.x) {
        int base = tile << 4;
        __syncthreads();
        for (int i = tid; i < 16 * 32; i += 256) {
            int r = i >> 5, c4 = i & 31;
            int node = base + r;
            float4 v = (node < N) ? ((const float4*)x)[(size_t)node * 32 + c4]
                                  : make_float4(0.f, 0.f, 0.f, 0.f);
            *(float4*)&sX[r][c4 * 4] = v;
        }
        __syncthreads();
        float a0 = 0.f, a1 = 0.f, a2 = 0.f, a3 = 0.f;
#pragma unroll 8
        for (int i = 0; i < 32; i++) {
            float4 w  = *(const float4*)&sW[ch][i * 4];
            float4 x0 = *(const float4*)&sX[g * 4 + 0][i * 4];
            float4 x1 = *(const float4*)&sX[g * 4 + 1][i * 4];
            float4 x2 = *(const float4*)&sX[g * 4 + 2][i * 4];
            float4 x3 = *(const float4*)&sX[g * 4 + 3][i * 4];
            a0 += w.x * x0.x + w.y * x0.y + w.z * x0.z + w.w * x0.w;
            a1 += w.x * x1.x + w.y * x1.y + w.z * x1.z + w.w * x1.w;
            a2 += w.x * x2.x + w.y * x2.y + w.z * x2.z + w.w * x2.w;
            a3 += w.x * x3.x + w.y * x3.y + w.z * x3.z + w.w * x3.w;
        }
        int n0 = base + g * 4;
        if (n0 + 0 < N) g_xh[(size_t)(n0 + 0) * 64 + ch] = a0;
        if (n0 + 1 < N) g_xh[(size_t)(n0 + 1) * 64 + ch] = a1;
        if (n0 + 2 < N) g_xh[(size_t)(n0 + 2) * 64 + ch] = a2;
        if (n0 + 3 < N) g_xh[(size_t)(n0 + 3) * 64 + ch] = a3;
    }
}

// ---------------- K1b: per-node attention scalars ---------------------------
__global__ void k_attn_nd(const float* __restrict__ att_src,
                          const float* __restrict__ att_dst, int N) {
    int t = blockIdx.x * blockDim.x + threadIdx.x;
    if (t >= N * 4) return;
    int n = t >> 2, h = t & 3;
    const float* xr = &g_xh[(size_t)n * 64 + h * 16];
    float as = 0.f, ad = 0.f;
#pragma unroll
    for (int c = 0; c < 16; c++) {
        float v = xr[c];
        as += v * att_src[h * 16 + c];
        ad += v * att_dst[h * 16 + c];
    }
    g_asrc[t] = as;
    g_adst[t] = ad;
}

// ---------------- K2: per-edge a_edge + logits + segment stats --------------
// warp per edge; lane covers 2 edge_attr features.  edge_index is INT32.
__global__ void k_edge(const float* __restrict__ ea, const int* __restrict__ ei, int E) {
    int lane = threadIdx.x & 31;
    int w  = (blockIdx.x * blockDim.x + threadIdx.x) >> 5;
    int nw = (gridDim.x * blockDim.x) >> 5;
    const float4* vp = (const float4*)g_v;
    float4 va = vp[2 * lane];
    float4 vb = vp[2 * lane + 1];
    for (int e = w; e < E; e += nw) {
        float2 a = *(const float2*)(ea + (size_t)e * 64 + lane * 2);
        float p0 = a.x * va.x + a.y * vb.x;
        float p1 = a.x * va.y + a.y * vb.y;
        float p2 = a.x * va.z + a.y * vb.z;
        float p3 = a.x * va.w + a.y * vb.w;
#pragma unroll
        for (int off = 16; off; off >>= 1) {
            p0 += __shfl_xor_sync(0xffffffffu, p0, off);
            p1 += __shfl_xor_sync(0xffffffffu, p1, off);
            p2 += __shfl_xor_sync(0xffffffffu, p2, off);
            p3 += __shfl_xor_sync(0xffffffffu, p3, off);
        }
        if (lane == 0) {
            int src = ei[e];
            int dst = ei[E + e];
            float4 as = *(const float4*)&g_asrc[src * 4];
            float4 ad = *(const float4*)&g_adst[dst * 4];
            float l0 = lrelu(as.x + ad.x + p0);
            float l1 = lrelu(as.y + ad.y + p1);
            float l2 = lrelu(as.z + ad.z + p2);
            float l3 = lrelu(as.w + ad.w + p3);
            *(float4*)&g_l[(size_t)e * 4] = make_float4(l0, l1, l2, l3);
            atomicMax(&g_amax[dst * 4 + 0], enc_f(l0));
            atomicMax(&g_amax[dst * 4 + 1], enc_f(l1));
            atomicMax(&g_amax[dst * 4 + 2], enc_f(l2));
            atomicMax(&g_amax[dst * 4 + 3], enc_f(l3));
            atomicAdd(&g_aes[dst * 4 + 0], p0);
            atomicAdd(&g_aes[dst * 4 + 1], p1);
            atomicAdd(&g_aes[dst * 4 + 2], p2);
            atomicAdd(&g_aes[dst * 4 + 3], p3);
            atomicAdd(&g_cnt[dst], 1.f);
        }
    }
}

// ---------------- K3: self-loop logits ---------------------------------------
__global__ void k_self(int N, int E) {
    int n = blockIdx.x * blockDim.x + threadIdx.x;
    if (n >= N) return;
    float c  = fmaxf(g_cnt[n], 1.f);
    float4 s  = *(const float4*)&g_aes[n * 4];
    float4 as = *(const float4*)&g_asrc[n * 4];
    float4 ad = *(const float4*)&g_adst[n * 4];
    float l0 = lrelu(as.x + ad.x + s.x / c);
    float l1 = lrelu(as.y + ad.y + s.y / c);
    float l2 = lrelu(as.z + ad.z + s.z / c);
    float l3 = lrelu(as.w + ad.w + s.w / c);
    *(float4*)&g_l[(size_t)(E + n) * 4] = make_float4(l0, l1, l2, l3);
    atomicMax(&g_amax[n * 4 + 0], enc_f(l0));
    atomicMax(&g_amax[n * 4 + 1], enc_f(l1));
    atomicMax(&g_amax[n * 4 + 2], enc_f(l2));
    atomicMax(&g_amax[n * 4 + 3], enc_f(l3));
}

// ---------------- K4: exp(l - amax) + denom ----------------------------------
__global__ void k_exp(const int* __restrict__ ei, int N, int E) {
    int t = blockIdx.x * blockDim.x + threadIdx.x;
    int T = (E + N) * 4;
    if (t >= T) return;
    int e = t >> 2, h = t & 3;
    int dst = (e < E) ? ei[E + e] : (e - E);
    float m  = dec_f(g_amax[dst * 4 + h]);
    float ex = __expf(g_l[t] - m);
    g_l[t] = ex;
    atomicAdd(&g_denom[dst * 4 + h], ex);
}

// ---------------- K5: weighted gather-scatter aggregation --------------------
// warp per edge; lane handles channels {lane, lane+32}
__global__ void k_agg(const int* __restrict__ ei, float* __restrict__ out,
                      int N, int E) {
    int lane = threadIdx.x & 31;
    int w  = (blockIdx.x * blockDim.x + threadIdx.x) >> 5;
    int nw = (gridDim.x * blockDim.x) >> 5;
    int total = E + N;
    int h0 = lane >> 4;        // head for channel `lane`
    for (int e = w; e < total; e += nw) {
        int src, dst;
        if (e < E) { src = __ldg(ei + e); dst = __ldg(ei + E + e); }
        else       { src = dst = e - E; }
        float w0 = __ldg(&g_l[(size_t)e * 4 + h0])     / (__ldg(&g_denom[dst * 4 + h0])     + 1e-16f);
        float w1 = __ldg(&g_l[(size_t)e * 4 + h0 + 2]) / (__ldg(&g_denom[dst * 4 + h0 + 2]) + 1e-16f);
        float x0 = __ldg(&g_xh[(size_t)src * 64 + lane]);
        float x1 = __ldg(&g_xh[(size_t)src * 64 + 32 + lane]);
        atomicAdd(out + (size_t)dst * 64 + lane,      x0 * w0);
        atomicAdd(out + (size_t)dst * 64 + 32 + lane, x1 * w1);
    }
}

// ---------------- K6: add bias ------------------------------------------------
__global__ void k_bias(float* __restrict__ out, const float* __restrict__ bias, int N) {
    int t = blockIdx.x * blockDim.x + threadIdx.x;
    if (t < N * 64) out[t] += bias[t & 63];
}

// -----------------------------------------------------------------------------
extern "C" void kernel_launch(void* const* d_in, const int* in_sizes, int n_in,
                              void* d_out, int out_size) {
    (void)n_in; (void)out_size;
    const float* x        = (const float*)d_in[0];
    const int*   ei       = (const int*)d_in[1];     // int32 (JAX x64 disabled)
    const float* ea       = (const float*)d_in[2];
    const float* W        = (const float*)d_in[3];
    const float* We       = (const float*)d_in[4];
    const float* att_src  = (const float*)d_in[5];
    const float* att_dst  = (const float*)d_in[6];
    const float* att_edge = (const float*)d_in[7];
    const float* bias     = (const float*)d_in[8];
    float* out = (float*)d_out;

    int N = in_sizes[0] / 128;   // x is [N,128]
    int E = in_sizes[1] / 2;     // edge_index is [2,E]

    int Z = N * 64;
    k_zero   <<<(Z + 255) / 256, 256>>>(out, N);
    k_vedge  <<<1, 256>>>(We, att_edge);
    k_xh     <<<740, 256>>>(x, W, N);
    k_attn_nd<<<(N * 4 + 255) / 256, 256>>>(att_src, att_dst, N);
    k_edge   <<<1184, 256>>>(ea, ei, E);
    k_self   <<<(N + 255) / 256, 256>>>(N, E);
    k_exp    <<<((E + N) * 4 + 255) / 256, 256>>>(ei, N, E);
    k_agg    <<<2048, 256>>>(ei, out, N, E);
    k_bias   <<<(Z + 255) / 256, 256>>>(out, bias, N);
}

// round 3
// speedup vs baseline: 1.2647x; 1.2647x over previous
#include <cuda_runtime.h>

// ---------------- static device scratch (no allocations allowed) -------------
#define MAXN 50176
#define MAXE 800256
#define CAP  128   // per-warp smem edge cache in k_node

__device__ __align__(16) float g_xh[(size_t)MAXN * 64];      // x @ W^T      [N,64]
__device__ __align__(16) float g_asrc[MAXN * 4];             // att_src . xh [N,4]
__device__ __align__(16) float g_adst[MAXN * 4];             // att_dst . xh [N,4]
__device__ __align__(16) float g_p[(size_t)MAXE * 4];        // a_edge per edge [E,4]
__device__ __align__(16) float g_ps[(size_t)MAXE * 4];       // sorted p / logits / alpha
__device__            int  g_src_s[MAXE];                    // sorted src index
__device__            int  g_deg[MAXN];                      // in-degree
__device__            int  g_ptr[MAXN];                      // CSR row starts
__device__            int  g_off[MAXN];                      // scatter cursor
__device__ __align__(16) float g_v[64 * 4];                  // folded W_edge/att_edge

__device__ __forceinline__ float lrelu(float f) { return f > 0.f ? f : 0.2f * f; }

__device__ __forceinline__ float4 wsum4(float4 v) {
#pragma unroll
    for (int o = 16; o; o >>= 1) {
        v.x += __shfl_xor_sync(0xffffffffu, v.x, o);
        v.y += __shfl_xor_sync(0xffffffffu, v.y, o);
        v.z += __shfl_xor_sync(0xffffffffu, v.z, o);
        v.w += __shfl_xor_sync(0xffffffffu, v.w, o);
    }
    return v;
}
__device__ __forceinline__ float4 wmax4(float4 v) {
#pragma unroll
    for (int o = 16; o; o >>= 1) {
        v.x = fmaxf(v.x, __shfl_xor_sync(0xffffffffu, v.x, o));
        v.y = fmaxf(v.y, __shfl_xor_sync(0xffffffffu, v.y, o));
        v.z = fmaxf(v.z, __shfl_xor_sync(0xffffffffu, v.z, o));
        v.w = fmaxf(v.w, __shfl_xor_sync(0xffffffffu, v.w, o));
    }
    return v;
}

// ---------------- K0: zero degree histogram ----------------------------------
__global__ void k_init(int N) {
    int t = blockIdx.x * blockDim.x + threadIdx.x;
    if (t < N) g_deg[t] = 0;
}

// ---------------- Kv: fold W_edge with att_edge: v[d][h] ----------------------
__global__ void k_vedge(const float* __restrict__ We, const float* __restrict__ att_edge) {
    int t = threadIdx.x;           // 256 = 64 d * 4 h
    int d = t >> 2, h = t & 3;
    float s = 0.f;
#pragma unroll
    for (int c = 0; c < 16; c++)
        s += We[(h * 16 + c) * 64 + d] * att_edge[h * 16 + c];
    g_v[d * 4 + h] = s;
}

// ---------------- K1: xh = x @ W^T + fused a_src/a_dst epilogue --------------
__global__ void k_xh(const float* __restrict__ x, const float* __restrict__ W,
                     const float* __restrict__ att_src, const float* __restrict__ att_dst,
                     int N) {
    __shared__ float sW[64][132];
    __shared__ float sX[16][132];
    int tid = threadIdx.x;          // 256
    for (int i = tid; i < 64 * 32; i += 256) {
        int r = i >> 5, c4 = i & 31;
        float4 w = ((const float4*)W)[r * 32 + c4];
        *(float4*)&sW[r][c4 * 4] = w;
    }
    int ch = tid & 63, g = tid >> 6;
    float ats = att_src[ch], atd = att_dst[ch];   // ch == h*16+c exactly
    int tiles = (N + 15) >> 4;
    for (int tile = blockIdx.x; tile < tiles; tile += gridDim.x) {
        int base = tile << 4;
        __syncthreads();
        for (int i = tid; i < 16 * 32; i += 256) {
            int r = i >> 5, c4 = i & 31;
            int node = base + r;
            float4 v = (node < N) ? ((const float4*)x)[(size_t)node * 32 + c4]
                                  : make_float4(0.f, 0.f, 0.f, 0.f);
            *(float4*)&sX[r][c4 * 4] = v;
        }
        __syncthreads();
        float a[4] = {0.f, 0.f, 0.f, 0.f};
#pragma unroll 8
        for (int i = 0; i < 32; i++) {
            float4 w = *(const float4*)&sW[ch][i * 4];
#pragma unroll
            for (int j = 0; j < 4; j++) {
                float4 xv = *(const float4*)&sX[g * 4 + j][i * 4];
                a[j] += w.x * xv.x + w.y * xv.y + w.z * xv.z + w.w * xv.w;
            }
        }
        int n0 = base + g * 4;
#pragma unroll
        for (int j = 0; j < 4; j++) {
            if (n0 + j < N) g_xh[(size_t)(n0 + j) * 64 + ch] = a[j];
            // fused attention scalars: reduce a[j]*att over the 16 channels of a head
            float s = a[j] * ats, d = a[j] * atd;
#pragma unroll
            for (int o = 8; o; o >>= 1) {
                s += __shfl_xor_sync(0xffffffffu, s, o);
                d += __shfl_xor_sync(0xffffffffu, d, o);
            }
            if ((ch & 15) == 0 && n0 + j < N) {
                int head = ch >> 4;
                g_asrc[(n0 + j) * 4 + head] = s;
                g_adst[(n0 + j) * 4 + head] = d;
            }
        }
    }
}

// ---------------- K2: per-edge a_edge (p) + degree histogram ------------------
__global__ void k_edge_p(const float* __restrict__ ea, const int* __restrict__ ei, int E) {
    int lane = threadIdx.x & 31;
    int w  = (blockIdx.x * blockDim.x + threadIdx.x) >> 5;
    int nw = (gridDim.x * blockDim.x) >> 5;
    const float4* vp = (const float4*)g_v;
    float4 va = vp[2 * lane];
    float4 vb = vp[2 * lane + 1];
    for (int e = w; e < E; e += nw) {
        float2 a = *(const float2*)(ea + (size_t)e * 64 + lane * 2);
        float4 p;
        p.x = a.x * va.x + a.y * vb.x;
        p.y = a.x * va.y + a.y * vb.y;
        p.z = a.x * va.z + a.y * vb.z;
        p.w = a.x * va.w + a.y * vb.w;
        p = wsum4(p);
        if (lane == 0) {
            *(float4*)&g_p[(size_t)e * 4] = p;
            atomicAdd(&g_deg[ei[E + e]], 1);
        }
    }
}

// ---------------- K3: single-block exclusive scan of degrees ------------------
__global__ void k_scan(int N) {
    __shared__ int sh[1024];
    int t = threadIdx.x;
    int chunk = (N + 1023) >> 10;
    int b = t * chunk, e = min(N, b + chunk);
    int s = 0;
    for (int i = b; i < e; i++) s += g_deg[i];
    sh[t] = s;
    __syncthreads();
    for (int o = 1; o < 1024; o <<= 1) {
        int u = (t >= o) ? sh[t - o] : 0;
        __syncthreads();
        sh[t] += u;
        __syncthreads();
    }
    int off = sh[t] - s;   // exclusive
    for (int i = b; i < e; i++) {
        int d = g_deg[i];
        g_ptr[i] = off;
        g_off[i] = off;
        off += d;
    }
}

// ---------------- K4: scatter edges into dst-sorted order --------------------
__global__ void k_scatter(const int* __restrict__ ei, int E) {
    int e = blockIdx.x * blockDim.x + threadIdx.x;
    if (e >= E) return;
    int src = ei[e], dst = ei[E + e];
    int pos = atomicAdd(&g_off[dst], 1);
    g_src_s[pos] = src;
    ((float4*)g_ps)[pos] = ((const float4*)g_p)[e];
}

// ---------------- K5: per-node softmax + aggregation (warp per node) ---------
__global__ void __launch_bounds__(256) k_node(const float* __restrict__ bias,
                                              float* __restrict__ out, int N) {
    __shared__ float4 s_al[8][CAP];
    __shared__ int    s_src[8][CAP];
    int lane = threadIdx.x & 31, wi = threadIdx.x >> 5;
    int warp  = (blockIdx.x * blockDim.x + threadIdx.x) >> 5;
    int nwarp = (gridDim.x * blockDim.x) >> 5;
    float bs0 = bias[lane], bs1 = bias[32 + lane];
    bool lo = lane < 16;

    for (int n = warp; n < N; n += nwarp) {
        int beg = g_ptr[n], deg = g_deg[n];
        float4 ad = ((const float4*)g_adst)[n];
        float4 an = ((const float4*)g_asrc)[n];

        // phase 1: logits, running max, sum of raw p (for self-loop attr mean)
        float4 m  = make_float4(-1e30f, -1e30f, -1e30f, -1e30f);
        float4 sp = make_float4(0.f, 0.f, 0.f, 0.f);
        for (int i = lane; i < deg; i += 32) {
            int src  = g_src_s[beg + i];
            float4 p = ((const float4*)g_ps)[beg + i];
            float4 as = ((const float4*)g_asrc)[src];
            float4 l;
            l.x = lrelu(as.x + ad.x + p.x);
            l.y = lrelu(as.y + ad.y + p.y);
            l.z = lrelu(as.z + ad.z + p.z);
            l.w = lrelu(as.w + ad.w + p.w);
            sp.x += p.x; sp.y += p.y; sp.z += p.z; sp.w += p.w;
            if (i < CAP) { s_al[wi][i] = l; s_src[wi][i] = src; }
            else         { ((float4*)g_ps)[beg + i] = l; }
            m.x = fmaxf(m.x, l.x); m.y = fmaxf(m.y, l.y);
            m.z = fmaxf(m.z, l.z); m.w = fmaxf(m.w, l.w);
        }
        m  = wmax4(m);
        sp = wsum4(sp);
        float c = fmaxf((float)deg, 1.f);
        float4 lsf;
        lsf.x = lrelu(an.x + ad.x + sp.x / c);
        lsf.y = lrelu(an.y + ad.y + sp.y / c);
        lsf.z = lrelu(an.z + ad.z + sp.z / c);
        lsf.w = lrelu(an.w + ad.w + sp.w / c);
        m.x = fmaxf(m.x, lsf.x); m.y = fmaxf(m.y, lsf.y);
        m.z = fmaxf(m.z, lsf.z); m.w = fmaxf(m.w, lsf.w);

        // phase 1b: exp + denom
        float4 d4 = make_float4(0.f, 0.f, 0.f, 0.f);
        for (int i = lane; i < deg; i += 32) {
            float4 l = (i < CAP) ? s_al[wi][i] : ((const float4*)g_ps)[beg + i];
            float4 e4;
            e4.x = __expf(l.x - m.x); e4.y = __expf(l.y - m.y);
            e4.z = __expf(l.z - m.z); e4.w = __expf(l.w - m.w);
            d4.x += e4.x; d4.y += e4.y; d4.z += e4.z; d4.w += e4.w;
            if (i < CAP) s_al[wi][i] = e4;
            else         ((float4*)g_ps)[beg + i] = e4;
        }
        d4 = wsum4(d4);
        float4 esf;
        esf.x = __expf(lsf.x - m.x); esf.y = __expf(lsf.y - m.y);
        esf.z = __expf(lsf.z - m.z); esf.w = __expf(lsf.w - m.w);
        d4.x += esf.x; d4.y += esf.y; d4.z += esf.z; d4.w += esf.w;
        float4 inv;
        inv.x = 1.f / (d4.x + 1e-16f); inv.y = 1.f / (d4.y + 1e-16f);
        inv.z = 1.f / (d4.z + 1e-16f); inv.w = 1.f / (d4.w + 1e-16f);
        if (deg > CAP) __threadfence_block();
        __syncwarp();

        // phase 2: channel-parallel weighted aggregation (lane = channel, +32)
        float acc0 = 0.f, acc1 = 0.f;
        for (int j = 0; j < deg; j++) {
            float4 a4;
            int src;
            if (j < CAP) { a4 = s_al[wi][j]; src = s_src[wi][j]; }
            else         { a4 = ((const float4*)g_ps)[beg + j]; src = g_src_s[beg + j]; }
            float w01 = lo ? a4.x * inv.x : a4.y * inv.y;
            float w23 = lo ? a4.z * inv.z : a4.w * inv.w;
            acc0 += w01 * g_xh[(size_t)src * 64 + lane];
            acc1 += w23 * g_xh[(size_t)src * 64 + 32 + lane];
        }
        // self-loop contribution
        float w01 = lo ? esf.x * inv.x : esf.y * inv.y;
        float w23 = lo ? esf.z * inv.z : esf.w * inv.w;
        acc0 += w01 * g_xh[(size_t)n * 64 + lane];
        acc1 += w23 * g_xh[(size_t)n * 64 + 32 + lane];

        out[(size_t)n * 64 + lane]      = acc0 + bs0;
        out[(size_t)n * 64 + 32 + lane] = acc1 + bs1;
        __syncwarp();   // smem reuse safety across node iterations
    }
}

// -----------------------------------------------------------------------------
extern "C" void kernel_launch(void* const* d_in, const int* in_sizes, int n_in,
                              void* d_out, int out_size) {
    (void)n_in; (void)out_size;
    const float* x        = (const float*)d_in[0];
    const int*   ei       = (const int*)d_in[1];
    const float* ea       = (const float*)d_in[2];
    const float* W        = (const float*)d_in[3];
    const float* We       = (const float*)d_in[4];
    const float* att_src  = (const float*)d_in[5];
    const float* att_dst  = (const float*)d_in[6];
    const float* att_edge = (const float*)d_in[7];
    const float* bias     = (const float*)d_in[8];
    float* out = (float*)d_out;

    int N = in_sizes[0] / 128;   // x is [N,128]
    int E = in_sizes[1] / 2;     // edge_index is [2,E]

    k_init   <<<(N + 255) / 256, 256>>>(N);
    k_vedge  <<<1, 256>>>(We, att_edge);
    k_xh     <<<740, 256>>>(x, W, att_src, att_dst, N);
    k_edge_p <<<1184, 256>>>(ea, ei, E);
    k_scan   <<<1, 1024>>>(N);
    k_scatter<<<(E + 255) / 256, 256>>>(ei, E);
    k_node   <<<1480, 256>>>(bias, out, N);
}

// round 4
// speedup vs baseline: 1.4775x; 1.1682x over previous
#include <cuda_runtime.h>

// ---------------- static device scratch (no allocations allowed) -------------
#define MAXN 50176
#define MAXE 800256
#define CAP  128   // per-warp smem edge cache in k_node

__device__ __align__(16) float g_xh[(size_t)MAXN * 64];      // x @ W^T      [N,64]
__device__ __align__(16) float g_asrc[MAXN * 4];             // att_src . xh [N,4]
__device__ __align__(16) float g_adst[MAXN * 4];             // att_dst . xh [N,4]
__device__ __align__(16) float g_ps[(size_t)MAXE * 4];       // dst-sorted p / logits / alpha
__device__            int  g_src_s[MAXE];                    // dst-sorted src index
__device__            int  g_deg[MAXN];                      // in-degree
__device__            int  g_ptr[MAXN];                      // CSR row starts
__device__            int  g_off[MAXN];                      // scatter cursor
__device__ __align__(16) float g_v[64 * 4];                  // folded W_edge/att_edge [feat][head]

__device__ __forceinline__ float lrelu(float f) { return f > 0.f ? f : 0.2f * f; }

__device__ __forceinline__ float4 wsum4(float4 v) {
#pragma unroll
    for (int o = 16; o; o >>= 1) {
        v.x += __shfl_xor_sync(0xffffffffu, v.x, o);
        v.y += __shfl_xor_sync(0xffffffffu, v.y, o);
        v.z += __shfl_xor_sync(0xffffffffu, v.z, o);
        v.w += __shfl_xor_sync(0xffffffffu, v.w, o);
    }
    return v;
}
__device__ __forceinline__ float4 wmax4(float4 v) {
#pragma unroll
    for (int o = 16; o; o >>= 1) {
        v.x = fmaxf(v.x, __shfl_xor_sync(0xffffffffu, v.x, o));
        v.y = fmaxf(v.y, __shfl_xor_sync(0xffffffffu, v.y, o));
        v.z = fmaxf(v.z, __shfl_xor_sync(0xffffffffu, v.z, o));
        v.w = fmaxf(v.w, __shfl_xor_sync(0xffffffffu, v.w, o));
    }
    return v;
}

// ---------------- K0: zero degree histogram ----------------------------------
__global__ void k_init(int N) {
    int t = blockIdx.x * blockDim.x + threadIdx.x;
    if (t < N) g_deg[t] = 0;
}

// ---------------- K0b: in-degree histogram ------------------------------------
__global__ void k_hist(const int* __restrict__ ei, int E) {
    int e = blockIdx.x * blockDim.x + threadIdx.x;
    if (e < E) atomicAdd(&g_deg[ei[E + e]], 1);
}

// ---------------- Kv: fold W_edge with att_edge: v[d][h] ----------------------
__global__ void k_vedge(const float* __restrict__ We, const float* __restrict__ att_edge) {
    int t = threadIdx.x;           // 256 = 64 d * 4 h
    int d = t >> 2, h = t & 3;
    float s = 0.f;
#pragma unroll
    for (int c = 0; c < 16; c++)
        s += We[(h * 16 + c) * 64 + d] * att_edge[h * 16 + c];
    g_v[d * 4 + h] = s;
}

// ---------------- K1: xh = x @ W^T + fused a_src/a_dst epilogue --------------
__global__ void k_xh(const float* __restrict__ x, const float* __restrict__ W,
                     const float* __restrict__ att_src, const float* __restrict__ att_dst,
                     int N) {
    __shared__ float sW[64][132];
    __shared__ float sX[16][132];
    int tid = threadIdx.x;          // 256
    for (int i = tid; i < 64 * 32; i += 256) {
        int r = i >> 5, c4 = i & 31;
        float4 w = ((const float4*)W)[r * 32 + c4];
        *(float4*)&sW[r][c4 * 4] = w;
    }
    int ch = tid & 63, g = tid >> 6;
    float ats = att_src[ch], atd = att_dst[ch];   // ch == h*16+c exactly
    int tiles = (N + 15) >> 4;
    for (int tile = blockIdx.x; tile < tiles; tile += gridDim.x) {
        int base = tile << 4;
        __syncthreads();
        for (int i = tid; i < 16 * 32; i += 256) {
            int r = i >> 5, c4 = i & 31;
            int node = base + r;
            float4 v = (node < N) ? ((const float4*)x)[(size_t)node * 32 + c4]
                                  : make_float4(0.f, 0.f, 0.f, 0.f);
            *(float4*)&sX[r][c4 * 4] = v;
        }
        __syncthreads();
        float a[4] = {0.f, 0.f, 0.f, 0.f};
#pragma unroll 8
        for (int i = 0; i < 32; i++) {
            float4 w = *(const float4*)&sW[ch][i * 4];
#pragma unroll
            for (int j = 0; j < 4; j++) {
                float4 xv = *(const float4*)&sX[g * 4 + j][i * 4];
                a[j] += w.x * xv.x + w.y * xv.y + w.z * xv.z + w.w * xv.w;
            }
        }
        int n0 = base + g * 4;
#pragma unroll
        for (int j = 0; j < 4; j++) {
            if (n0 + j < N) g_xh[(size_t)(n0 + j) * 64 + ch] = a[j];
            float s = a[j] * ats, d = a[j] * atd;
#pragma unroll
            for (int o = 8; o; o >>= 1) {
                s += __shfl_xor_sync(0xffffffffu, s, o);
                d += __shfl_xor_sync(0xffffffffu, d, o);
            }
            if ((ch & 15) == 0 && n0 + j < N) {
                int head = ch >> 4;
                g_asrc[(n0 + j) * 4 + head] = s;
                g_adst[(n0 + j) * 4 + head] = d;
            }
        }
    }
}

// ---------------- K3: single-block exclusive scan of degrees ------------------
__global__ void k_scan(int N) {
    __shared__ int sh[1024];
    int t = threadIdx.x;
    int chunk = (N + 1023) >> 10;
    int b = t * chunk, e = min(N, b + chunk);
    int s = 0;
    for (int i = b; i < e; i++) s += g_deg[i];
    sh[t] = s;
    __syncthreads();
    for (int o = 1; o < 1024; o <<= 1) {
        int u = (t >= o) ? sh[t - o] : 0;
        __syncthreads();
        sh[t] += u;
        __syncthreads();
    }
    int off = sh[t] - s;   // exclusive
    for (int i = b; i < e; i++) {
        int d = g_deg[i];
        g_ptr[i] = off;
        g_off[i] = off;
        off += d;
    }
}

// ---------------- K2: staged thread-per-edge p + direct sorted scatter --------
// block = 128 threads, tile = 128 edges. edge_attr tile is contiguous -> fully
// coalesced staging; padded smem rows (17 float4) keep LDS.128 bank-clean.
__global__ void __launch_bounds__(128) k_edge_p(const float* __restrict__ ea,
                                                const int* __restrict__ ei, int E) {
    __shared__ float4 sE[128 * 17];
    __shared__ float4 sV[64];
    int tid = threadIdx.x;
    int tile0 = blockIdx.x * 128;
    if (tid < 64) sV[tid] = ((const float4*)g_v)[tid];
    const float4* ea4 = (const float4*)ea;
#pragma unroll
    for (int i = tid; i < 128 * 16; i += 128) {
        int row = i >> 4, col = i & 15;
        if (tile0 + row < E)
            sE[row * 17 + col] = ea4[(size_t)(tile0 + row) * 16 + col];
    }
    __syncthreads();
    int e = tile0 + tid;
    if (e >= E) return;
    float4 acc = make_float4(0.f, 0.f, 0.f, 0.f);
#pragma unroll
    for (int k = 0; k < 16; k++) {
        float4 a  = sE[tid * 17 + k];
        float4 v0 = sV[4 * k + 0];
        float4 v1 = sV[4 * k + 1];
        float4 v2 = sV[4 * k + 2];
        float4 v3 = sV[4 * k + 3];
        acc.x += a.x * v0.x + a.y * v1.x + a.z * v2.x + a.w * v3.x;
        acc.y += a.x * v0.y + a.y * v1.y + a.z * v2.y + a.w * v3.y;
        acc.z += a.x * v0.z + a.y * v1.z + a.z * v2.z + a.w * v3.z;
        acc.w += a.x * v0.w + a.y * v1.w + a.z * v2.w + a.w * v3.w;
    }
    int src = ei[e], dst = ei[E + e];
    int pos = atomicAdd(&g_off[dst], 1);
    g_src_s[pos] = src;
    ((float4*)g_ps)[pos] = acc;
}

// ---------------- K5: per-node softmax + aggregation (warp per node) ---------
__global__ void __launch_bounds__(256) k_node(const float* __restrict__ bias,
                                              float* __restrict__ out, int N) {
    __shared__ float4 s_al[8][CAP];
    __shared__ int    s_src[8][CAP];
    int lane = threadIdx.x & 31, wi = threadIdx.x >> 5;
    int warp  = (blockIdx.x * blockDim.x + threadIdx.x) >> 5;
    int nwarp = (gridDim.x * blockDim.x) >> 5;
    float bs0 = bias[lane], bs1 = bias[32 + lane];
    bool lo = lane < 16;

    for (int n = warp; n < N; n += nwarp) {
        int beg = g_ptr[n], deg = g_deg[n];
        float4 ad = ((const float4*)g_adst)[n];
        float4 an = ((const float4*)g_asrc)[n];

        // phase 1: logits, running max, sum of raw p (self-loop attr mean)
        float4 m  = make_float4(-1e30f, -1e30f, -1e30f, -1e30f);
        float4 sp = make_float4(0.f, 0.f, 0.f, 0.f);
        for (int i = lane; i < deg; i += 32) {
            int src  = g_src_s[beg + i];
            float4 p = ((const float4*)g_ps)[beg + i];
            float4 as = ((const float4*)g_asrc)[src];
            float4 l;
            l.x = lrelu(as.x + ad.x + p.x);
            l.y = lrelu(as.y + ad.y + p.y);
            l.z = lrelu(as.z + ad.z + p.z);
            l.w = lrelu(as.w + ad.w + p.w);
            sp.x += p.x; sp.y += p.y; sp.z += p.z; sp.w += p.w;
            if (i < CAP) { s_al[wi][i] = l; s_src[wi][i] = src; }
            else         { ((float4*)g_ps)[beg + i] = l; }
            m.x = fmaxf(m.x, l.x); m.y = fmaxf(m.y, l.y);
            m.z = fmaxf(m.z, l.z); m.w = fmaxf(m.w, l.w);
        }
        m  = wmax4(m);
        sp = wsum4(sp);
        float c = fmaxf((float)deg, 1.f);
        float4 lsf;
        lsf.x = lrelu(an.x + ad.x + sp.x / c);
        lsf.y = lrelu(an.y + ad.y + sp.y / c);
        lsf.z = lrelu(an.z + ad.z + sp.z / c);
        lsf.w = lrelu(an.w + ad.w + sp.w / c);
        m.x = fmaxf(m.x, lsf.x); m.y = fmaxf(m.y, lsf.y);
        m.z = fmaxf(m.z, lsf.z); m.w = fmaxf(m.w, lsf.w);

        // phase 1b: exp + denom
        float4 d4 = make_float4(0.f, 0.f, 0.f, 0.f);
        for (int i = lane; i < deg; i += 32) {
            float4 l = (i < CAP) ? s_al[wi][i] : ((const float4*)g_ps)[beg + i];
            float4 e4;
            e4.x = __expf(l.x - m.x); e4.y = __expf(l.y - m.y);
            e4.z = __expf(l.z - m.z); e4.w = __expf(l.w - m.w);
            d4.x += e4.x; d4.y += e4.y; d4.z += e4.z; d4.w += e4.w;
            if (i < CAP) s_al[wi][i] = e4;
            else         ((float4*)g_ps)[beg + i] = e4;
        }
        d4 = wsum4(d4);
        float4 esf;
        esf.x = __expf(lsf.x - m.x); esf.y = __expf(lsf.y - m.y);
        esf.z = __expf(lsf.z - m.z); esf.w = __expf(lsf.w - m.w);
        d4.x += esf.x; d4.y += esf.y; d4.z += esf.z; d4.w += esf.w;
        float4 inv;
        inv.x = 1.f / (d4.x + 1e-16f); inv.y = 1.f / (d4.y + 1e-16f);
        inv.z = 1.f / (d4.z + 1e-16f); inv.w = 1.f / (d4.w + 1e-16f);
        if (deg > CAP) __threadfence_block();
        __syncwarp();

        // phase 2: channel-parallel weighted aggregation (lane = channel, +32)
        float acc0 = 0.f, acc1 = 0.f;
        for (int j = 0; j < deg; j++) {
            float4 a4;
            int src;
            if (j < CAP) { a4 = s_al[wi][j]; src = s_src[wi][j]; }
            else         { a4 = ((const float4*)g_ps)[beg + j]; src = g_src_s[beg + j]; }
            float w01 = lo ? a4.x * inv.x : a4.y * inv.y;
            float w23 = lo ? a4.z * inv.z : a4.w * inv.w;
            acc0 += w01 * g_xh[(size_t)src * 64 + lane];
            acc1 += w23 * g_xh[(size_t)src * 64 + 32 + lane];
        }
        // self-loop contribution
        float w01 = lo ? esf.x * inv.x : esf.y * inv.y;
        float w23 = lo ? esf.z * inv.z : esf.w * inv.w;
        acc0 += w01 * g_xh[(size_t)n * 64 + lane];
        acc1 += w23 * g_xh[(size_t)n * 64 + 32 + lane];

        out[(size_t)n * 64 + lane]      = acc0 + bs0;
        out[(size_t)n * 64 + 32 + lane] = acc1 + bs1;
        __syncwarp();   // smem reuse safety across node iterations
    }
}

// -----------------------------------------------------------------------------
extern "C" void kernel_launch(void* const* d_in, const int* in_sizes, int n_in,
                              void* d_out, int out_size) {
    (void)n_in; (void)out_size;
    const float* x        = (const float*)d_in[0];
    const int*   ei       = (const int*)d_in[1];
    const float* ea       = (const float*)d_in[2];
    const float* W        = (const float*)d_in[3];
    const float* We       = (const float*)d_in[4];
    const float* att_src  = (const float*)d_in[5];
    const float* att_dst  = (const float*)d_in[6];
    const float* att_edge = (const float*)d_in[7];
    const float* bias     = (const float*)d_in[8];
    float* out = (float*)d_out;

    int N = in_sizes[0] / 128;   // x is [N,128]
    int E = in_sizes[1] / 2;     // edge_index is [2,E]

    k_init   <<<(N + 255) / 256, 256>>>(N);
    k_hist   <<<(E + 255) / 256, 256>>>(ei, E);
    k_vedge  <<<1, 256>>>(We, att_edge);
    k_scan   <<<1, 1024>>>(N);
    k_xh     <<<740, 256>>>(x, W, att_src, att_dst, N);
    k_edge_p <<<(E + 127) / 128, 128>>>(ea, ei, E);
    k_node   <<<1480, 256>>>(bias, out, N);
}

// round 5
// speedup vs baseline: 2.0233x; 1.3694x over previous
#include <cuda_runtime.h>

// ---------------- static device scratch (no allocations allowed) -------------
#define MAXN 50176
#define MAXE 800256
#define CAP  128   // per-warp smem edge cache in k_node
#define SCAN_B 256 // elements per scan block

__device__ __align__(16) float g_xh[(size_t)MAXN * 64];      // x @ W^T      [N,64]
__device__ __align__(16) float g_asrc[MAXN * 4];             // att_src . xh [N,4]
__device__ __align__(16) float g_adst[MAXN * 4];             // att_dst . xh [N,4]
__device__ __align__(16) float g_ps[(size_t)MAXE * 4];       // dst-sorted p / logits / alpha
__device__            int  g_src_s[MAXE];                    // dst-sorted src index
__device__            int  g_deg[MAXN];                      // in-degree
__device__            int  g_ptr[MAXN];                      // CSR row starts
__device__            int  g_off[MAXN];                      // scatter cursor
__device__            int  g_bsum[(MAXN + SCAN_B - 1) / SCAN_B + 1];
__device__ __align__(16) float g_v[64 * 4];                  // folded W_edge/att_edge [feat][head]

__device__ __forceinline__ float lrelu(float f) { return f > 0.f ? f : 0.2f * f; }

__device__ __forceinline__ float4 wsum4(float4 v) {
#pragma unroll
    for (int o = 16; o; o >>= 1) {
        v.x += __shfl_xor_sync(0xffffffffu, v.x, o);
        v.y += __shfl_xor_sync(0xffffffffu, v.y, o);
        v.z += __shfl_xor_sync(0xffffffffu, v.z, o);
        v.w += __shfl_xor_sync(0xffffffffu, v.w, o);
    }
    return v;
}
__device__ __forceinline__ float4 wmax4(float4 v) {
#pragma unroll
    for (int o = 16; o; o >>= 1) {
        v.x = fmaxf(v.x, __shfl_xor_sync(0xffffffffu, v.x, o));
        v.y = fmaxf(v.y, __shfl_xor_sync(0xffffffffu, v.y, o));
        v.z = fmaxf(v.z, __shfl_xor_sync(0xffffffffu, v.z, o));
        v.w = fmaxf(v.w, __shfl_xor_sync(0xffffffffu, v.w, o));
    }
    return v;
}

// ---------------- K0: zero degree histogram ----------------------------------
__global__ void k_init(int N) {
    int t = blockIdx.x * blockDim.x + threadIdx.x;
    if (t < N) g_deg[t] = 0;
}

// ---------------- K0b: in-degree histogram ------------------------------------
__global__ void k_hist(const int* __restrict__ ei, int E) {
    int e = blockIdx.x * blockDim.x + threadIdx.x;
    if (e < E) atomicAdd(&g_deg[ei[E + e]], 1);
}

// ---------------- Kv: fold W_edge with att_edge: v[d][h] ----------------------
__global__ void k_vedge(const float* __restrict__ We, const float* __restrict__ att_edge) {
    int t = threadIdx.x;           // 256 = 64 d * 4 h
    int d = t >> 2, h = t & 3;
    float s = 0.f;
#pragma unroll
    for (int c = 0; c < 16; c++)
        s += We[(h * 16 + c) * 64 + d] * att_edge[h * 16 + c];
    g_v[d * 4 + h] = s;
}

// ---------------- multi-block exclusive scan of degrees -----------------------
// A: per-block sums
__global__ void k_scanA(int N) {
    __shared__ int sh[SCAN_B];
    int t = threadIdx.x, b = blockIdx.x;
    int i = b * SCAN_B + t;
    sh[t] = (i < N) ? g_deg[i] : 0;
    __syncthreads();
#pragma unroll
    for (int o = SCAN_B / 2; o; o >>= 1) {
        if (t < o) sh[t] += sh[t + o];
        __syncthreads();
    }
    if (t == 0) g_bsum[b] = sh[0];
}
// B: exclusive scan of block sums (single block; NB <= 1024)
__global__ void k_scanB(int NB) {
    __shared__ int sh[1024];
    int t = threadIdx.x;
    int v = (t < NB) ? g_bsum[t] : 0;
    sh[t] = v;
    __syncthreads();
    for (int o = 1; o < 1024; o <<= 1) {
        int u = (t >= o) ? sh[t - o] : 0;
        __syncthreads();
        sh[t] += u;
        __syncthreads();
    }
    if (t < NB) g_bsum[t] = sh[t] - v;   // exclusive
}
// C: block-local exclusive scan + block offset -> g_ptr / g_off
__global__ void k_scanC(int N) {
    __shared__ int sh[SCAN_B];
    int t = threadIdx.x, b = blockIdx.x;
    int i = b * SCAN_B + t;
    int v = (i < N) ? g_deg[i] : 0;
    sh[t] = v;
    __syncthreads();
#pragma unroll
    for (int o = 1; o < SCAN_B; o <<= 1) {
        int u = (t >= o) ? sh[t - o] : 0;
        __syncthreads();
        sh[t] += u;
        __syncthreads();
    }
    if (i < N) {
        int off = g_bsum[b] + sh[t] - v;   // exclusive
        g_ptr[i] = off;
        g_off[i] = off;
    }
}

// ---------------- K1: xh = x @ W^T + fused a_src/a_dst epilogue --------------
__global__ void k_xh(const float* __restrict__ x, const float* __restrict__ W,
                     const float* __restrict__ att_src, const float* __restrict__ att_dst,
                     int N) {
    __shared__ float sW[64][132];
    __shared__ float sX[16][132];
    int tid = threadIdx.x;          // 256
    for (int i = tid; i < 64 * 32; i += 256) {
        int r = i >> 5, c4 = i & 31;
        float4 w = ((const float4*)W)[r * 32 + c4];
        *(float4*)&sW[r][c4 * 4] = w;
    }
    int ch = tid & 63, g = tid >> 6;
    float ats = att_src[ch], atd = att_dst[ch];   // ch == h*16+c exactly
    int tiles = (N + 15) >> 4;
    for (int tile = blockIdx.x; tile < tiles; tile += gridDim.x) {
        int base = tile << 4;
        __syncthreads();
        for (int i = tid; i < 16 * 32; i += 256) {
            int r = i >> 5, c4 = i & 31;
            int node = base + r;
            float4 v = (node < N) ? ((const float4*)x)[(size_t)node * 32 + c4]
                                  : make_float4(0.f, 0.f, 0.f, 0.f);
            *(float4*)&sX[r][c4 * 4] = v;
        }
        __syncthreads();
        float a[4] = {0.f, 0.f, 0.f, 0.f};
#pragma unroll 8
        for (int i = 0; i < 32; i++) {
            float4 w = *(const float4*)&sW[ch][i * 4];
#pragma unroll
            for (int j = 0; j < 4; j++) {
                float4 xv = *(const float4*)&sX[g * 4 + j][i * 4];
                a[j] += w.x * xv.x + w.y * xv.y + w.z * xv.z + w.w * xv.w;
            }
        }
        int n0 = base + g * 4;
#pragma unroll
        for (int j = 0; j < 4; j++) {
            if (n0 + j < N) g_xh[(size_t)(n0 + j) * 64 + ch] = a[j];
            float s = a[j] * ats, d = a[j] * atd;
#pragma unroll
            for (int o = 8; o; o >>= 1) {
                s += __shfl_xor_sync(0xffffffffu, s, o);
                d += __shfl_xor_sync(0xffffffffu, d, o);
            }
            if ((ch & 15) == 0 && n0 + j < N) {
                int head = ch >> 4;
                g_asrc[(n0 + j) * 4 + head] = s;
                g_adst[(n0 + j) * 4 + head] = d;
            }
        }
    }
}

// ---------------- K2: staged thread-per-edge p + direct sorted scatter --------
__global__ void __launch_bounds__(128) k_edge_p(const float* __restrict__ ea,
                                                const int* __restrict__ ei, int E) {
    __shared__ float4 sE[128 * 17];
    __shared__ float4 sV[64];
    int tid = threadIdx.x;
    int tile0 = blockIdx.x * 128;
    if (tid < 64) sV[tid] = ((const float4*)g_v)[tid];
    const float4* ea4 = (const float4*)ea;
#pragma unroll
    for (int i = tid; i < 128 * 16; i += 128) {
        int row = i >> 4, col = i & 15;
        if (tile0 + row < E)
            sE[row * 17 + col] = ea4[(size_t)(tile0 + row) * 16 + col];
    }
    __syncthreads();
    int e = tile0 + tid;
    if (e >= E) return;
    float4 acc = make_float4(0.f, 0.f, 0.f, 0.f);
#pragma unroll
    for (int k = 0; k < 16; k++) {
        float4 a  = sE[tid * 17 + k];
        float4 v0 = sV[4 * k + 0];
        float4 v1 = sV[4 * k + 1];
        float4 v2 = sV[4 * k + 2];
        float4 v3 = sV[4 * k + 3];
        acc.x += a.x * v0.x + a.y * v1.x + a.z * v2.x + a.w * v3.x;
        acc.y += a.x * v0.y + a.y * v1.y + a.z * v2.y + a.w * v3.y;
        acc.z += a.x * v0.z + a.y * v1.z + a.z * v2.z + a.w * v3.z;
        acc.w += a.x * v0.w + a.y * v1.w + a.z * v2.w + a.w * v3.w;
    }
    int src = ei[e], dst = ei[E + e];
    int pos = atomicAdd(&g_off[dst], 1);
    g_src_s[pos] = src;
    ((float4*)g_ps)[pos] = acc;
}

// ---------------- K5: per-node softmax + aggregation (warp per node) ---------
__global__ void __launch_bounds__(256) k_node(const float* __restrict__ bias,
                                              float* __restrict__ out, int N) {
    __shared__ float4 s_al[8][CAP];
    __shared__ int    s_src[8][CAP];
    int lane = threadIdx.x & 31, wi = threadIdx.x >> 5;
    int warp  = (blockIdx.x * blockDim.x + threadIdx.x) >> 5;
    int nwarp = (gridDim.x * blockDim.x) >> 5;
    float bs0 = bias[lane], bs1 = bias[32 + lane];
    bool lo = lane < 16;

    for (int n = warp; n < N; n += nwarp) {
        int beg = g_ptr[n], deg = g_deg[n];
        float4 ad = ((const float4*)g_adst)[n];
        float4 an = ((const float4*)g_asrc)[n];

        // phase 1: logits, running max, sum of raw p (self-loop attr mean)
        float4 m  = make_float4(-1e30f, -1e30f, -1e30f, -1e30f);
        float4 sp = make_float4(0.f, 0.f, 0.f, 0.f);
        for (int i = lane; i < deg; i += 32) {
            int src  = g_src_s[beg + i];
            float4 p = ((const float4*)g_ps)[beg + i];
            float4 as = ((const float4*)g_asrc)[src];
            float4 l;
            l.x = lrelu(as.x + ad.x + p.x);
            l.y = lrelu(as.y + ad.y + p.y);
            l.z = lrelu(as.z + ad.z + p.z);
            l.w = lrelu(as.w + ad.w + p.w);
            sp.x += p.x; sp.y += p.y; sp.z += p.z; sp.w += p.w;
            if (i < CAP) { s_al[wi][i] = l; s_src[wi][i] = src; }
            else         { ((float4*)g_ps)[beg + i] = l; }
            m.x = fmaxf(m.x, l.x); m.y = fmaxf(m.y, l.y);
            m.z = fmaxf(m.z, l.z); m.w = fmaxf(m.w, l.w);
        }
        m  = wmax4(m);
        sp = wsum4(sp);
        float c = fmaxf((float)deg, 1.f);
        float4 lsf;
        lsf.x = lrelu(an.x + ad.x + sp.x / c);
        lsf.y = lrelu(an.y + ad.y + sp.y / c);
        lsf.z = lrelu(an.z + ad.z + sp.z / c);
        lsf.w = lrelu(an.w + ad.w + sp.w / c);
        m.x = fmaxf(m.x, lsf.x); m.y = fmaxf(m.y, lsf.y);
        m.z = fmaxf(m.z, lsf.z); m.w = fmaxf(m.w, lsf.w);

        // phase 1b: exp + denom
        float4 d4 = make_float4(0.f, 0.f, 0.f, 0.f);
        for (int i = lane; i < deg; i += 32) {
            float4 l = (i < CAP) ? s_al[wi][i] : ((const float4*)g_ps)[beg + i];
            float4 e4;
            e4.x = __expf(l.x - m.x); e4.y = __expf(l.y - m.y);
            e4.z = __expf(l.z - m.z); e4.w = __expf(l.w - m.w);
            d4.x += e4.x; d4.y += e4.y; d4.z += e4.z; d4.w += e4.w;
            if (i < CAP) s_al[wi][i] = e4;
            else         ((float4*)g_ps)[beg + i] = e4;
        }
        d4 = wsum4(d4);
        float4 esf;
        esf.x = __expf(lsf.x - m.x); esf.y = __expf(lsf.y - m.y);
        esf.z = __expf(lsf.z - m.z); esf.w = __expf(lsf.w - m.w);
        d4.x += esf.x; d4.y += esf.y; d4.z += esf.z; d4.w += esf.w;
        float4 inv;
        inv.x = 1.f / (d4.x + 1e-16f); inv.y = 1.f / (d4.y + 1e-16f);
        inv.z = 1.f / (d4.z + 1e-16f); inv.w = 1.f / (d4.w + 1e-16f);
        if (deg > CAP) __threadfence_block();
        __syncwarp();

        // phase 2: channel-parallel weighted aggregation (lane = channel, +32)
        float acc0 = 0.f, acc1 = 0.f;
        for (int j = 0; j < deg; j++) {
            float4 a4;
            int src;
            if (j < CAP) { a4 = s_al[wi][j]; src = s_src[wi][j]; }
            else         { a4 = ((const float4*)g_ps)[beg + j]; src = g_src_s[beg + j]; }
            float w01 = lo ? a4.x * inv.x : a4.y * inv.y;
            float w23 = lo ? a4.z * inv.z : a4.w * inv.w;
            acc0 += w01 * g_xh[(size_t)src * 64 + lane];
            acc1 += w23 * g_xh[(size_t)src * 64 + 32 + lane];
        }
        // self-loop contribution
        float w01 = lo ? esf.x * inv.x : esf.y * inv.y;
        float w23 = lo ? esf.z * inv.z : esf.w * inv.w;
        acc0 += w01 * g_xh[(size_t)n * 64 + lane];
        acc1 += w23 * g_xh[(size_t)n * 64 + 32 + lane];

        out[(size_t)n * 64 + lane]      = acc0 + bs0;
        out[(size_t)n * 64 + 32 + lane] = acc1 + bs1;
        __syncwarp();   // smem reuse safety across node iterations
    }
}

// -----------------------------------------------------------------------------
extern "C" void kernel_launch(void* const* d_in, const int* in_sizes, int n_in,
                              void* d_out, int out_size) {
    (void)n_in; (void)out_size;
    const float* x        = (const float*)d_in[0];
    const int*   ei       = (const int*)d_in[1];
    const float* ea       = (const float*)d_in[2];
    const float* W        = (const float*)d_in[3];
    const float* We       = (const float*)d_in[4];
    const float* att_src  = (const float*)d_in[5];
    const float* att_dst  = (const float*)d_in[6];
    const float* att_edge = (const float*)d_in[7];
    const float* bias     = (const float*)d_in[8];
    float* out = (float*)d_out;

    int N = in_sizes[0] / 128;   // x is [N,128]
    int E = in_sizes[1] / 2;     // edge_index is [2,E]
    int NB = (N + SCAN_B - 1) / SCAN_B;

    k_init   <<<(N + 255) / 256, 256>>>(N);
    k_hist   <<<(E + 255) / 256, 256>>>(ei, E);
    k_vedge  <<<1, 256>>>(We, att_edge);
    k_scanA  <<<NB, SCAN_B>>>(N);
    k_scanB  <<<1, 1024>>>(NB);
    k_scanC  <<<NB, SCAN_B>>>(N);
    k_xh     <<<740, 256>>>(x, W, att_src, att_dst, N);
    k_edge_p <<<(E + 127) / 128, 128>>>(ea, ei, E);
    k_node   <<<1480, 256>>>(bias, out, N);
}

// round 6
// speedup vs baseline: 2.1073x; 1.0415x over previous
#include <cuda_runtime.h>

// ---------------- static device scratch (no allocations allowed) -------------
#define MAXN 50176
#define MAXE 800256
#define CAP  64    // per-warp smem edge cache in k_node (deg max ~45 for this graph)
#define SCAN_B 256 // elements per scan block

__device__ __align__(16) float g_xh[(size_t)MAXN * 64];      // x @ W^T      [N,64]
__device__ __align__(16) float g_asrc[MAXN * 4];             // att_src . xh [N,4]
__device__ __align__(16) float g_adst[MAXN * 4];             // att_dst . xh [N,4]
__device__ __align__(16) float g_ps[(size_t)MAXE * 4];       // dst-sorted p / logits / alpha
__device__            int  g_src_s[MAXE];                    // dst-sorted src index
__device__            int  g_deg[MAXN];                      // in-degree
__device__            int  g_ptr[MAXN];                      // CSR row starts
__device__            int  g_off[MAXN];                      // scatter cursor
__device__            int  g_bsum[(MAXN + SCAN_B - 1) / SCAN_B + 1];
__device__ __align__(16) float g_v[64 * 4];                  // folded W_edge/att_edge [feat][head]

__device__ __forceinline__ float lrelu(float f) { return f > 0.f ? f : 0.2f * f; }

__device__ __forceinline__ float4 wsum4(float4 v) {
#pragma unroll
    for (int o = 16; o; o >>= 1) {
        v.x += __shfl_xor_sync(0xffffffffu, v.x, o);
        v.y += __shfl_xor_sync(0xffffffffu, v.y, o);
        v.z += __shfl_xor_sync(0xffffffffu, v.z, o);
        v.w += __shfl_xor_sync(0xffffffffu, v.w, o);
    }
    return v;
}
__device__ __forceinline__ float4 wmax4(float4 v) {
#pragma unroll
    for (int o = 16; o; o >>= 1) {
        v.x = fmaxf(v.x, __shfl_xor_sync(0xffffffffu, v.x, o));
        v.y = fmaxf(v.y, __shfl_xor_sync(0xffffffffu, v.y, o));
        v.z = fmaxf(v.z, __shfl_xor_sync(0xffffffffu, v.z, o));
        v.w = fmaxf(v.w, __shfl_xor_sync(0xffffffffu, v.w, o));
    }
    return v;
}

// ---------------- K0: zero degree histogram ----------------------------------
__global__ void k_init(int N) {
    int t = blockIdx.x * blockDim.x + threadIdx.x;
    if (t < N) g_deg[t] = 0;
}

// ---------------- K0b: in-degree histogram ------------------------------------
__global__ void k_hist(const int* __restrict__ ei, int E) {
    int e = blockIdx.x * blockDim.x + threadIdx.x;
    if (e < E) atomicAdd(&g_deg[ei[E + e]], 1);
}

// ---------------- Kv: fold W_edge with att_edge: v[d][h] ----------------------
__global__ void k_vedge(const float* __restrict__ We, const float* __restrict__ att_edge) {
    int t = threadIdx.x;           // 256 = 64 d * 4 h
    int d = t >> 2, h = t & 3;
    float s = 0.f;
#pragma unroll
    for (int c = 0; c < 16; c++)
        s += We[(h * 16 + c) * 64 + d] * att_edge[h * 16 + c];
    g_v[d * 4 + h] = s;
}

// ---------------- multi-block exclusive scan of degrees -----------------------
__global__ void k_scanA(int N) {
    __shared__ int sh[SCAN_B];
    int t = threadIdx.x, b = blockIdx.x;
    int i = b * SCAN_B + t;
    sh[t] = (i < N) ? g_deg[i] : 0;
    __syncthreads();
#pragma unroll
    for (int o = SCAN_B / 2; o; o >>= 1) {
        if (t < o) sh[t] += sh[t + o];
        __syncthreads();
    }
    if (t == 0) g_bsum[b] = sh[0];
}
__global__ void k_scanB(int NB) {
    __shared__ int sh[1024];
    int t = threadIdx.x;
    int v = (t < NB) ? g_bsum[t] : 0;
    sh[t] = v;
    __syncthreads();
    for (int o = 1; o < 1024; o <<= 1) {
        int u = (t >= o) ? sh[t - o] : 0;
        __syncthreads();
        sh[t] += u;
        __syncthreads();
    }
    if (t < NB) g_bsum[t] = sh[t] - v;   // exclusive
}
__global__ void k_scanC(int N) {
    __shared__ int sh[SCAN_B];
    int t = threadIdx.x, b = blockIdx.x;
    int i = b * SCAN_B + t;
    int v = (i < N) ? g_deg[i] : 0;
    sh[t] = v;
    __syncthreads();
#pragma unroll
    for (int o = 1; o < SCAN_B; o <<= 1) {
        int u = (t >= o) ? sh[t - o] : 0;
        __syncthreads();
        sh[t] += u;
        __syncthreads();
    }
    if (i < N) {
        int off = g_bsum[b] + sh[t] - v;   // exclusive
        g_ptr[i] = off;
        g_off[i] = off;
    }
}

// ---------------- K1: xh = x @ W^T + fused a_src/a_dst epilogue --------------
__global__ void k_xh(const float* __restrict__ x, const float* __restrict__ W,
                     const float* __restrict__ att_src, const float* __restrict__ att_dst,
                     int N) {
    __shared__ float sW[64][132];
    __shared__ float sX[16][132];
    int tid = threadIdx.x;          // 256
    for (int i = tid; i < 64 * 32; i += 256) {
        int r = i >> 5, c4 = i & 31;
        float4 w = ((const float4*)W)[r * 32 + c4];
        *(float4*)&sW[r][c4 * 4] = w;
    }
    int ch = tid & 63, g = tid >> 6;
    float ats = att_src[ch], atd = att_dst[ch];   // ch == h*16+c exactly
    int tiles = (N + 15) >> 4;
    for (int tile = blockIdx.x; tile < tiles; tile += gridDim.x) {
        int base = tile << 4;
        __syncthreads();
        for (int i = tid; i < 16 * 32; i += 256) {
            int r = i >> 5, c4 = i & 31;
            int node = base + r;
            float4 v = (node < N) ? ((const float4*)x)[(size_t)node * 32 + c4]
                                  : make_float4(0.f, 0.f, 0.f, 0.f);
            *(float4*)&sX[r][c4 * 4] = v;
        }
        __syncthreads();
        float a[4] = {0.f, 0.f, 0.f, 0.f};
#pragma unroll 8
        for (int i = 0; i < 32; i++) {
            float4 w = *(const float4*)&sW[ch][i * 4];
#pragma unroll
            for (int j = 0; j < 4; j++) {
                float4 xv = *(const float4*)&sX[g * 4 + j][i * 4];
                a[j] += w.x * xv.x + w.y * xv.y + w.z * xv.z + w.w * xv.w;
            }
        }
        int n0 = base + g * 4;
#pragma unroll
        for (int j = 0; j < 4; j++) {
            if (n0 + j < N) g_xh[(size_t)(n0 + j) * 64 + ch] = a[j];
            float s = a[j] * ats, d = a[j] * atd;
#pragma unroll
            for (int o = 8; o; o >>= 1) {
                s += __shfl_xor_sync(0xffffffffu, s, o);
                d += __shfl_xor_sync(0xffffffffu, d, o);
            }
            if ((ch & 15) == 0 && n0 + j < N) {
                int head = ch >> 4;
                g_asrc[(n0 + j) * 4 + head] = s;
                g_adst[(n0 + j) * 4 + head] = d;
            }
        }
    }
}

// ---------------- K2: staged thread-per-edge p + direct sorted scatter --------
__global__ void __launch_bounds__(128) k_edge_p(const float* __restrict__ ea,
                                                const int* __restrict__ ei, int E) {
    __shared__ float4 sE[128 * 17];
    __shared__ float4 sV[64];
    int tid = threadIdx.x;
    int tile0 = blockIdx.x * 128;
    if (tid < 64) sV[tid] = ((const float4*)g_v)[tid];
    const float4* ea4 = (const float4*)ea;
#pragma unroll
    for (int i = tid; i < 128 * 16; i += 128) {
        int row = i >> 4, col = i & 15;
        if (tile0 + row < E)
            sE[row * 17 + col] = ea4[(size_t)(tile0 + row) * 16 + col];
    }
    __syncthreads();
    int e = tile0 + tid;
    if (e >= E) return;
    float4 acc = make_float4(0.f, 0.f, 0.f, 0.f);
#pragma unroll
    for (int k = 0; k < 16; k++) {
        float4 a  = sE[tid * 17 + k];
        float4 v0 = sV[4 * k + 0];
        float4 v1 = sV[4 * k + 1];
        float4 v2 = sV[4 * k + 2];
        float4 v3 = sV[4 * k + 3];
        acc.x += a.x * v0.x + a.y * v1.x + a.z * v2.x + a.w * v3.x;
        acc.y += a.x * v0.y + a.y * v1.y + a.z * v2.y + a.w * v3.y;
        acc.z += a.x * v0.z + a.y * v1.z + a.z * v2.z + a.w * v3.z;
        acc.w += a.x * v0.w + a.y * v1.w + a.z * v2.w + a.w * v3.w;
    }
    int src = ei[e], dst = ei[E + e];
    int pos = atomicAdd(&g_off[dst], 1);
    g_src_s[pos] = src;
    ((float4*)g_ps)[pos] = acc;
}

// ---------------- K5: per-node softmax + aggregation (warp per node) ---------
__global__ void __launch_bounds__(256) k_node(const float* __restrict__ bias,
                                              float* __restrict__ out, int N) {
    __shared__ float4 s_al[8][CAP];
    __shared__ int    s_src[8][CAP];
    int lane = threadIdx.x & 31, wi = threadIdx.x >> 5;
    int warp  = (blockIdx.x * blockDim.x + threadIdx.x) >> 5;
    int nwarp = (gridDim.x * blockDim.x) >> 5;
    float bs0 = bias[lane], bs1 = bias[32 + lane];
    bool lo = lane < 16;

    for (int n = warp; n < N; n += nwarp) {
        int beg = g_ptr[n], deg = g_deg[n];
        int dc  = min(deg, CAP);
        float4 ad = ((const float4*)g_adst)[n];
        float4 an = ((const float4*)g_asrc)[n];

        // ---- phase 1: logits, running max, sum of raw p -------------------
        float4 m  = make_float4(-1e30f, -1e30f, -1e30f, -1e30f);
        float4 sp = make_float4(0.f, 0.f, 0.f, 0.f);
        for (int i = lane; i < dc; i += 32) {
            int src  = g_src_s[beg + i];
            float4 p = ((const float4*)g_ps)[beg + i];
            float4 as = ((const float4*)g_asrc)[src];
            float4 l;
            l.x = lrelu(as.x + ad.x + p.x);
            l.y = lrelu(as.y + ad.y + p.y);
            l.z = lrelu(as.z + ad.z + p.z);
            l.w = lrelu(as.w + ad.w + p.w);
            sp.x += p.x; sp.y += p.y; sp.z += p.z; sp.w += p.w;
            s_al[wi][i] = l; s_src[wi][i] = src;
            m.x = fmaxf(m.x, l.x); m.y = fmaxf(m.y, l.y);
            m.z = fmaxf(m.z, l.z); m.w = fmaxf(m.w, l.w);
        }
        for (int i = CAP + lane; i < deg; i += 32) {   // rare spill path
            int src  = g_src_s[beg + i];
            float4 p = ((const float4*)g_ps)[beg + i];
            float4 as = ((const float4*)g_asrc)[src];
            float4 l;
            l.x = lrelu(as.x + ad.x + p.x);
            l.y = lrelu(as.y + ad.y + p.y);
            l.z = lrelu(as.z + ad.z + p.z);
            l.w = lrelu(as.w + ad.w + p.w);
            sp.x += p.x; sp.y += p.y; sp.z += p.z; sp.w += p.w;
            ((float4*)g_ps)[beg + i] = l;
            m.x = fmaxf(m.x, l.x); m.y = fmaxf(m.y, l.y);
            m.z = fmaxf(m.z, l.z); m.w = fmaxf(m.w, l.w);
        }
        m  = wmax4(m);
        sp = wsum4(sp);
        float c = fmaxf((float)deg, 1.f);
        float4 lsf;
        lsf.x = lrelu(an.x + ad.x + sp.x / c);
        lsf.y = lrelu(an.y + ad.y + sp.y / c);
        lsf.z = lrelu(an.z + ad.z + sp.z / c);
        lsf.w = lrelu(an.w + ad.w + sp.w / c);
        m.x = fmaxf(m.x, lsf.x); m.y = fmaxf(m.y, lsf.y);
        m.z = fmaxf(m.z, lsf.z); m.w = fmaxf(m.w, lsf.w);

        // ---- phase 1b: exp + denom ----------------------------------------
        float4 d4 = make_float4(0.f, 0.f, 0.f, 0.f);
        for (int i = lane; i < dc; i += 32) {
            float4 l = s_al[wi][i];
            float4 e4;
            e4.x = __expf(l.x - m.x); e4.y = __expf(l.y - m.y);
            e4.z = __expf(l.z - m.z); e4.w = __expf(l.w - m.w);
            d4.x += e4.x; d4.y += e4.y; d4.z += e4.z; d4.w += e4.w;
            s_al[wi][i] = e4;
        }
        for (int i = CAP + lane; i < deg; i += 32) {
            float4 l = ((const float4*)g_ps)[beg + i];
            float4 e4;
            e4.x = __expf(l.x - m.x); e4.y = __expf(l.y - m.y);
            e4.z = __expf(l.z - m.z); e4.w = __expf(l.w - m.w);
            d4.x += e4.x; d4.y += e4.y; d4.z += e4.z; d4.w += e4.w;
            ((float4*)g_ps)[beg + i] = e4;
        }
        d4 = wsum4(d4);
        float4 esf;
        esf.x = __expf(lsf.x - m.x); esf.y = __expf(lsf.y - m.y);
        esf.z = __expf(lsf.z - m.z); esf.w = __expf(lsf.w - m.w);
        d4.x += esf.x; d4.y += esf.y; d4.z += esf.z; d4.w += esf.w;
        float4 inv;
        inv.x = 1.f / (d4.x + 1e-16f); inv.y = 1.f / (d4.y + 1e-16f);
        inv.z = 1.f / (d4.z + 1e-16f); inv.w = 1.f / (d4.w + 1e-16f);
        float invA = lo ? inv.x : inv.y;
        float invB = lo ? inv.z : inv.w;
        if (deg > CAP) __threadfence_block();
        __syncwarp();

        // ---- phase 2: channel-parallel aggregation, unrolled x2 ------------
        float acc0 = 0.f, acc1 = 0.f;
        int j = 0;
        for (; j + 2 <= dc; j += 2) {
            float4 a0 = s_al[wi][j];
            float4 a1 = s_al[wi][j + 1];
            const float* r0 = &g_xh[(size_t)s_src[wi][j] * 64];
            const float* r1 = &g_xh[(size_t)s_src[wi][j + 1] * 64];
            float x00 = r0[lane], x01 = r0[32 + lane];
            float x10 = r1[lane], x11 = r1[32 + lane];
            acc0 += (lo ? a0.x : a0.y) * invA * x00;
            acc1 += (lo ? a0.z : a0.w) * invB * x01;
            acc0 += (lo ? a1.x : a1.y) * invA * x10;
            acc1 += (lo ? a1.z : a1.w) * invB * x11;
        }
        if (j < dc) {
            float4 a0 = s_al[wi][j];
            const float* r0 = &g_xh[(size_t)s_src[wi][j] * 64];
            acc0 += (lo ? a0.x : a0.y) * invA * r0[lane];
            acc1 += (lo ? a0.z : a0.w) * invB * r0[32 + lane];
        }
        for (int k = CAP; k < deg; k++) {   // rare spill path
            float4 a0 = ((const float4*)g_ps)[beg + k];
            const float* r0 = &g_xh[(size_t)g_src_s[beg + k] * 64];
            acc0 += (lo ? a0.x : a0.y) * invA * r0[lane];
            acc1 += (lo ? a0.z : a0.w) * invB * r0[32 + lane];
        }
        // self-loop contribution
        {
            const float* rn = &g_xh[(size_t)n * 64];
            acc0 += (lo ? esf.x : esf.y) * invA * rn[lane];
            acc1 += (lo ? esf.z : esf.w) * invB * rn[32 + lane];
        }
        out[(size_t)n * 64 + lane]      = acc0 + bs0;
        out[(size_t)n * 64 + 32 + lane] = acc1 + bs1;
        __syncwarp();   // smem reuse safety across node iterations
    }
}

// -----------------------------------------------------------------------------
extern "C" void kernel_launch(void* const* d_in, const int* in_sizes, int n_in,
                              void* d_out, int out_size) {
    (void)n_in; (void)out_size;
    const float* x        = (const float*)d_in[0];
    const int*   ei       = (const int*)d_in[1];
    const float* ea       = (const float*)d_in[2];
    const float* W        = (const float*)d_in[3];
    const float* We       = (const float*)d_in[4];
    const float* att_src  = (const float*)d_in[5];
    const float* att_dst  = (const float*)d_in[6];
    const float* att_edge = (const float*)d_in[7];
    const float* bias     = (const float*)d_in[8];
    float* out = (float*)d_out;

    int N = in_sizes[0] / 128;   // x is [N,128]
    int E = in_sizes[1] / 2;     // edge_index is [2,E]
    int NB = (N + SCAN_B - 1) / SCAN_B;

    k_init   <<<(N + 255) / 256, 256>>>(N);
    k_hist   <<<(E + 255) / 256, 256>>>(ei, E);
    k_vedge  <<<1, 256>>>(We, att_edge);
    k_scanA  <<<NB, SCAN_B>>>(N);
    k_scanB  <<<1, 1024>>>(NB);
    k_scanC  <<<NB, SCAN_B>>>(N);
    k_xh     <<<740, 256>>>(x, W, att_src, att_dst, N);
    k_edge_p <<<(E + 127) / 128, 128>>>(ea, ei, E);
    k_node   <<<1480, 256>>>(bias, out, N);
}